// round 1
// baseline (speedup 1.0000x reference)
#include <cuda_runtime.h>
#include <cuda_bf16.h>
#include <math.h>

// Problem constants
#define Bb   4
#define T    128
#define D    512
#define Hh   4
#define DK   128
#define NL   4
#define DFF  2048
#define NC   5

#define BTD  (Bb*T*D)        // 262144
#define BTT  (Bb*T*T)        // 65536

// ---------------- scratch (single __device__ array, no allocations) ----------
// layout (floats):
//  QE 0, AE, Qb, Kb, Vb, T0, T1, Hb  : 8 * BTD        = 2,097,152
//  FFN                               : Bb*T*DFF       = 1,048,576
//  QKb, Pb                           : 2 * BTT        = 131,072
//  EQb, EKb                          : 2 * Bb*T*NC    = 5,120
//  Gb                                : 32
//  Wb                                : Bb*T*NC        = 2,560
//  PKb                               : BTD            = 262,144
#define OFF_QE  0
#define OFF_AE  (OFF_QE + BTD)
#define OFF_Q   (OFF_AE + BTD)
#define OFF_K   (OFF_Q + BTD)
#define OFF_V   (OFF_K + BTD)
#define OFF_T0  (OFF_V + BTD)
#define OFF_T1  (OFF_T0 + BTD)
#define OFF_H   (OFF_T1 + BTD)
#define OFF_FFN (OFF_H + BTD)
#define OFF_QK  (OFF_FFN + Bb*T*DFF)
#define OFF_P   (OFF_QK + BTT)
#define OFF_EQ  (OFF_P + BTT)
#define OFF_EK  (OFF_EQ + Bb*T*NC)
#define OFF_G   (OFF_EK + Bb*T*NC)
#define OFF_W   (OFF_G + 32)
#define OFF_PK  (OFF_W + Bb*T*NC)
#define SCRATCH_TOTAL (OFF_PK + BTD)

__device__ float g_scratch[SCRATCH_TOTAL];

__device__ __forceinline__ float gelu_f(float x) {
    return 0.5f * x * (1.0f + erff(x * 0.7071067811865475f));
}

// ---------------- generic tiled SGEMM: C = A @ B (+bias) (+gelu), batched ----
// A: [M,K] (row-major), B: [K,N] or (transB) [N,K], C: [M,N].
// All M,N multiples of 64 and K multiple of 16 in this problem (no bounds checks).
#define BM 64
#define BN 64
#define BK 16

__global__ void gemm_kernel(const float* __restrict__ A, const float* __restrict__ Bm,
                            const float* __restrict__ bias, float* __restrict__ C,
                            int M, int N, int K, int transB, int act,
                            long long sA, long long sB, long long sC) {
    A  += (long long)blockIdx.z * sA;
    Bm += (long long)blockIdx.z * sB;
    C  += (long long)blockIdx.z * sC;

    __shared__ float As[BK][BM + 4];
    __shared__ float Bs[BK][BN];

    int tid = threadIdx.x;          // 256 threads
    int bm = blockIdx.y * BM;
    int bn = blockIdx.x * BN;
    int tr = tid >> 4;              // 0..15
    int tc = tid & 15;              // 0..15

    float acc[4][4] = {};

    for (int k0 = 0; k0 < K; k0 += BK) {
        // load A tile (BM x BK), coalesced over c
        #pragma unroll
        for (int i = tid; i < BM * BK; i += 256) {
            int r = i >> 4, c = i & 15;
            As[c][r] = A[(size_t)(bm + r) * K + k0 + c];
        }
        if (!transB) {
            #pragma unroll
            for (int i = tid; i < BK * BN; i += 256) {
                int r = i >> 6, c = i & 63;
                Bs[r][c] = Bm[(size_t)(k0 + r) * N + bn + c];
            }
        } else {
            #pragma unroll
            for (int i = tid; i < BK * BN; i += 256) {
                int r = i & 15, c = i >> 4;
                Bs[r][c] = Bm[(size_t)(bn + c) * K + k0 + r];
            }
        }
        __syncthreads();

        #pragma unroll
        for (int kk = 0; kk < BK; kk++) {
            float a[4], bv[4];
            #pragma unroll
            for (int i = 0; i < 4; i++) a[i] = As[kk][tr * 4 + i];
            #pragma unroll
            for (int j = 0; j < 4; j++) bv[j] = Bs[kk][tc * 4 + j];
            #pragma unroll
            for (int i = 0; i < 4; i++)
                #pragma unroll
                for (int j = 0; j < 4; j++)
                    acc[i][j] += a[i] * bv[j];
        }
        __syncthreads();
    }

    #pragma unroll
    for (int i = 0; i < 4; i++) {
        int r = bm + tr * 4 + i;
        #pragma unroll
        for (int j = 0; j < 4; j++) {
            int c = bn + tc * 4 + j;
            float v = acc[i][j] + (bias ? bias[c] : 0.0f);
            if (act) v = gelu_f(v);
            C[(size_t)r * N + c] = v;
        }
    }
}

// ---------------- LayerNorm kernels (row = one (b,t), 256 threads, D=512) ----
__global__ void add_pos_ln_kernel(const float* __restrict__ x, const float* __restrict__ pos,
                                  const float* __restrict__ w, const float* __restrict__ b,
                                  float* __restrict__ out) {
    int row = blockIdx.x;
    int t = row % T;
    int tid = threadIdx.x;
    __shared__ float red[256];

    float v0 = x[(size_t)row * D + tid]       + pos[(size_t)t * D + tid];
    float v1 = x[(size_t)row * D + tid + 256] + pos[(size_t)t * D + tid + 256];

    red[tid] = v0 + v1;
    __syncthreads();
    for (int off = 128; off > 0; off >>= 1) { if (tid < off) red[tid] += red[tid + off]; __syncthreads(); }
    float mean = red[0] * (1.0f / D);
    __syncthreads();
    float d0 = v0 - mean, d1 = v1 - mean;
    red[tid] = d0 * d0 + d1 * d1;
    __syncthreads();
    for (int off = 128; off > 0; off >>= 1) { if (tid < off) red[tid] += red[tid + off]; __syncthreads(); }
    float inv = rsqrtf(red[0] * (1.0f / D) + 1e-12f);

    out[(size_t)row * D + tid]       = w[tid] * d0 * inv + b[tid];
    out[(size_t)row * D + tid + 256] = w[tid + 256] * d1 * inv + b[tid + 256];
}

// x += y (persisted); out = LN(x) * w + b.   (out may alias x)
__global__ void residual_ln_kernel(float* __restrict__ x, const float* __restrict__ y,
                                   float* __restrict__ out,
                                   const float* __restrict__ w, const float* __restrict__ b) {
    int row = blockIdx.x;
    int tid = threadIdx.x;
    __shared__ float red[256];

    float v0 = x[(size_t)row * D + tid]       + y[(size_t)row * D + tid];
    float v1 = x[(size_t)row * D + tid + 256] + y[(size_t)row * D + tid + 256];
    x[(size_t)row * D + tid]       = v0;
    x[(size_t)row * D + tid + 256] = v1;

    red[tid] = v0 + v1;
    __syncthreads();
    for (int off = 128; off > 0; off >>= 1) { if (tid < off) red[tid] += red[tid + off]; __syncthreads(); }
    float mean = red[0] * (1.0f / D);
    __syncthreads();
    float d0 = v0 - mean, d1 = v1 - mean;
    red[tid] = d0 * d0 + d1 * d1;
    __syncthreads();
    for (int off = 128; off > 0; off >>= 1) { if (tid < off) red[tid] += red[tid + off]; __syncthreads(); }
    float inv = rsqrtf(red[0] * (1.0f / D) + 1e-12f);

    out[(size_t)row * D + tid]       = w[tid] * d0 * inv + b[tid];
    out[(size_t)row * D + tid + 256] = w[tid + 256] * d1 * inv + b[tid + 256];
}

// ---------------- MHA core: one block per (q-row, head, batch), 128 threads --
__global__ void attn_kernel(const float* __restrict__ q, const float* __restrict__ k,
                            const float* __restrict__ v, float* __restrict__ o) {
    int t = blockIdx.x, h = blockIdx.y, b = blockIdx.z;
    int j = threadIdx.x;                 // key index, then dim index
    __shared__ float qs[DK];
    __shared__ float sc[T];
    __shared__ float red[T];

    const float* qrow = q + ((size_t)(b * T + t)) * D + h * DK;
    qs[j] = qrow[j];
    __syncthreads();

    const float* krow = k + ((size_t)(b * T + j)) * D + h * DK;
    float s = 0.0f;
    #pragma unroll 8
    for (int d = 0; d < DK; d++) s += qs[d] * krow[d];
    s *= 0.08838834764831845f;           // 1/sqrt(128)

    red[j] = s; __syncthreads();
    for (int off = 64; off > 0; off >>= 1) { if (j < off) red[j] = fmaxf(red[j], red[j + off]); __syncthreads(); }
    float mx = red[0]; __syncthreads();
    float e = expf(s - mx);
    red[j] = e; __syncthreads();
    for (int off = 64; off > 0; off >>= 1) { if (j < off) red[j] += red[j + off]; __syncthreads(); }
    float inv = 1.0f / red[0];
    sc[j] = e * inv;
    __syncthreads();

    float acc = 0.0f;
    const float* vbase = v + ((size_t)(b * T)) * D + h * DK + j;
    for (int s2 = 0; s2 < T; s2++) acc += sc[s2] * vbase[(size_t)s2 * D];
    o[((size_t)(b * T + t)) * D + h * DK + j] = acc;
}

// ---------------- sim head helper kernels ------------------------------------
// out[row, c] = sum_d X[row,d] * E[c,d]   (row = b*T+t, 256 threads)
__global__ void edot_kernel(const float* __restrict__ X, const float* __restrict__ E,
                            float* __restrict__ out) {
    int row = blockIdx.x;
    int tid = threadIdx.x;
    __shared__ float red[NC * 256];
    float acc[NC] = {};
    for (int d = tid; d < D; d += 256) {
        float x = X[(size_t)row * D + d];
        #pragma unroll
        for (int c = 0; c < NC; c++) acc[c] += x * E[(size_t)c * D + d];
    }
    #pragma unroll
    for (int c = 0; c < NC; c++) red[c * 256 + tid] = acc[c];
    __syncthreads();
    for (int off = 128; off > 0; off >>= 1) {
        if (tid < off) {
            #pragma unroll
            for (int c = 0; c < NC; c++) red[c * 256 + tid] += red[c * 256 + tid + off];
        }
        __syncthreads();
    }
    if (tid < NC) out[(size_t)row * NC + tid] = red[tid * 256];
}

// G[c,c'] = E_c . E_c'
__global__ void gram_kernel(const float* __restrict__ E, float* __restrict__ G) {
    int i = threadIdx.x;
    if (i < NC * NC) {
        int c = i / NC, c2 = i % NC;
        float s = 0.0f;
        for (int d = 0; d < D; d++) s += E[(size_t)c * D + d] * E[(size_t)c2 * D + d];
        G[i] = s;
    }
}

// scores -> softmax -> sharpen-softmax -> P, and W[b,t,c] = sum_s P * R2
__global__ void sim_attn_kernel(const float* __restrict__ QK, const float* __restrict__ qa,
                                const float* __restrict__ aq, const float* __restrict__ Eq,
                                const float* __restrict__ Ek, const float* __restrict__ G,
                                float* __restrict__ P, float* __restrict__ Wout) {
    int t = blockIdx.x, b = blockIdx.y;
    int s = threadIdx.x;                 // 128 threads
    __shared__ float g[NC * NC];
    __shared__ float red[T];
    __shared__ float pv[T];
    if (s < NC * NC) g[s] = G[s];
    __syncthreads();

    float f1[NC], f2[NC];
    const float* r1 = qa + (((size_t)b * T + t) * T + s) * NC;   // qa_relation[b,t,s,:]
    const float* r2 = aq + (((size_t)b * T + s) * T + t) * NC;   // aq_relation[b,s,t,:]
    #pragma unroll
    for (int c = 0; c < NC; c++) { f1[c] = r1[c]; f2[c] = r2[c]; }

    float sc = QK[((size_t)b * T + t) * T + s];
    const float* eq = Eq + ((size_t)b * T + t) * NC;
    const float* ek = Ek + ((size_t)b * T + s) * NC;
    #pragma unroll
    for (int c = 0; c < NC; c++) sc += f1[c] * ek[c] + f2[c] * eq[c];
    #pragma unroll
    for (int c = 0; c < NC; c++)
        #pragma unroll
        for (int c2 = 0; c2 < NC; c2++)
            sc += f1[c] * g[c * NC + c2] * f2[c2];

    // softmax #1
    red[s] = sc; __syncthreads();
    for (int off = 64; off > 0; off >>= 1) { if (s < off) red[s] = fmaxf(red[s], red[s + off]); __syncthreads(); }
    float m1 = red[0]; __syncthreads();
    float e1 = expf(sc - m1);
    red[s] = e1; __syncthreads();
    for (int off = 64; off > 0; off >>= 1) { if (s < off) red[s] += red[s + off]; __syncthreads(); }
    float p = e1 / red[0];
    __syncthreads();

    // sharpening: softmax(1000*p), clipped (clip is a no-op but keep it)
    float l = 1000.0f * p;
    red[s] = l; __syncthreads();
    for (int off = 64; off > 0; off >>= 1) { if (s < off) red[s] = fmaxf(red[s], red[s + off]); __syncthreads(); }
    float m2 = red[0]; __syncthreads();
    float e2 = expf(l - m2);
    red[s] = e2; __syncthreads();
    for (int off = 64; off > 0; off >>= 1) { if (s < off) red[s] += red[s + off]; __syncthreads(); }
    float p2 = e2 / red[0];
    p2 = fminf(fmaxf(p2, 0.0f), 1.0f);
    __syncthreads();

    P[((size_t)b * T + t) * T + s] = p2;
    pv[s] = p2;
    __syncthreads();

    #pragma unroll
    for (int c = 0; c < NC; c++) {
        red[s] = pv[s] * f2[c];
        __syncthreads();
        for (int off = 64; off > 0; off >>= 1) { if (s < off) red[s] += red[s + off]; __syncthreads(); }
        if (s == 0) Wout[((size_t)b * T + t) * NC + c] = red[0];
        __syncthreads();
    }
}

// out[b,:] = mean_t(pk + W@E) @ cls_w + cls_b   (one block per b, 512 threads)
__global__ void final_kernel(const float* __restrict__ pk, const float* __restrict__ Wm,
                             const float* __restrict__ E, const float* __restrict__ clsw,
                             const float* __restrict__ clsb, float* __restrict__ out) {
    int b = blockIdx.x;
    int d = threadIdx.x;                 // 512 threads
    __shared__ float wm[NC];
    __shared__ float red[512];

    if (d < NC) {
        float s = 0.0f;
        for (int t = 0; t < T; t++) s += Wm[((size_t)b * T + t) * NC + d];
        wm[d] = s * (1.0f / T);
    }
    __syncthreads();

    float s = 0.0f;
    for (int t = 0; t < T; t++) s += pk[((size_t)b * T + t) * D + d];
    s *= (1.0f / T);
    #pragma unroll
    for (int c = 0; c < NC; c++) s += wm[c] * E[(size_t)c * D + d];

    for (int j = 0; j < 3; j++) {
        red[d] = s * clsw[(size_t)d * 3 + j];
        __syncthreads();
        for (int off = 256; off > 0; off >>= 1) { if (d < off) red[d] += red[d + off]; __syncthreads(); }
        if (d == 0) out[b * 3 + j] = red[0] + clsb[j];
        __syncthreads();
    }
}

// ---------------- host orchestration ----------------------------------------
static inline void launch_gemm(const float* A, const float* W, const float* bias, float* C,
                               int M, int N, int K, int transB, int act,
                               int batch, long long sA, long long sB, long long sC) {
    dim3 grid((N + BN - 1) / BN, (M + BM - 1) / BM, batch);
    gemm_kernel<<<grid, 256>>>(A, W, bias, C, M, N, K, transB, act, sA, sB, sC);
}

extern "C" void kernel_launch(void* const* d_in, const int* in_sizes, int n_in,
                              void* d_out, int out_size) {
    const float* q_emb   = (const float*)d_in[0];
    const float* a_emb   = (const float*)d_in[1];
    const float* qa_rel  = (const float*)d_in[2];
    const float* aq_rel  = (const float*)d_in[3];
    const float* conceptE= (const float*)d_in[4];
    const float* pos_emb = (const float*)d_in[5];
    const float* pe_w    = (const float*)d_in[6];
    const float* pe_b    = (const float*)d_in[7];
    const float* Wq      = (const float*)d_in[8];
    const float* bq      = (const float*)d_in[9];
    const float* Wk      = (const float*)d_in[10];
    const float* bk      = (const float*)d_in[11];
    const float* Wv      = (const float*)d_in[12];
    const float* bv      = (const float*)d_in[13];
    const float* Wo      = (const float*)d_in[14];
    const float* bo      = (const float*)d_in[15];
    const float* ff1w    = (const float*)d_in[16];
    const float* ff1b    = (const float*)d_in[17];
    const float* ff2w    = (const float*)d_in[18];
    const float* ff2b    = (const float*)d_in[19];
    const float* lninw   = (const float*)d_in[20];
    const float* lninb   = (const float*)d_in[21];
    const float* lnoutw  = (const float*)d_in[22];
    const float* lnoutb  = (const float*)d_in[23];
    const float* simWq   = (const float*)d_in[24];
    const float* simbq   = (const float*)d_in[25];
    const float* simWk   = (const float*)d_in[26];
    const float* simbk   = (const float*)d_in[27];
    const float* clsw    = (const float*)d_in[28];
    const float* clsb    = (const float*)d_in[29];
    float* out = (float*)d_out;

    float* base = nullptr;
    cudaGetSymbolAddress((void**)&base, g_scratch);

    float* QE  = base + OFF_QE;
    float* AE  = base + OFF_AE;
    float* Qb  = base + OFF_Q;
    float* Kb  = base + OFF_K;
    float* Vb  = base + OFF_V;
    float* T0  = base + OFF_T0;
    float* T1b = base + OFF_T1;
    float* Hb  = base + OFF_H;
    float* FFN = base + OFF_FFN;
    float* QKb = base + OFF_QK;
    float* Pb  = base + OFF_P;
    float* EQb = base + OFF_EQ;
    float* EKb = base + OFF_EK;
    float* Gb  = base + OFF_G;
    float* Wb  = base + OFF_W;
    float* PKb = base + OFF_PK;

    const int M = Bb * T;   // 512 rows

    // --- two encoder towers ---
    for (int e = 0; e < 2; e++) {
        const float* emb = e ? a_emb : q_emb;
        float* x = e ? AE : QE;

        add_pos_ln_kernel<<<M, 256>>>(emb, pos_emb, pe_w, pe_b, x);

        for (int i = 0; i < NL; i++) {
            const float* wq = Wq + (size_t)i * D * D;
            const float* wk = Wk + (size_t)i * D * D;
            const float* wv = Wv + (size_t)i * D * D;
            const float* wo = Wo + (size_t)i * D * D;

            launch_gemm(x, wq, bq + (size_t)i * D, Qb, M, D, D, 0, 0, 1, 0, 0, 0);
            launch_gemm(x, wk, bk + (size_t)i * D, Kb, M, D, D, 0, 0, 1, 0, 0, 0);
            launch_gemm(x, wv, bv + (size_t)i * D, Vb, M, D, D, 0, 0, 1, 0, 0, 0);

            attn_kernel<<<dim3(T, Hh, Bb), 128>>>(Qb, Kb, Vb, T0);

            launch_gemm(T0, wo, bo + (size_t)i * D, T1b, M, D, D, 0, 0, 1, 0, 0, 0);
            residual_ln_kernel<<<M, 256>>>(x, T1b, Hb, lninw + (size_t)i * D, lninb + (size_t)i * D);

            launch_gemm(Hb, ff1w + (size_t)i * D * DFF, ff1b + (size_t)i * DFF, FFN,
                        M, DFF, D, 0, /*gelu*/1, 1, 0, 0, 0);
            launch_gemm(FFN, ff2w + (size_t)i * DFF * D, ff2b + (size_t)i * D, T1b,
                        M, D, DFF, 0, 0, 1, 0, 0, 0);
            residual_ln_kernel<<<M, 256>>>(x, T1b, x, lnoutw + (size_t)i * D, lnoutb + (size_t)i * D);
        }
    }

    // --- sim-attention head (factored; never materializes hL/hR) ---
    launch_gemm(QE, simWq, simbq, Qb, M, D, D, 0, 0, 1, 0, 0, 0);   // q_sim
    launch_gemm(AE, simWk, simbk, Kb, M, D, D, 0, 0, 1, 0, 0, 0);   // k_sim

    edot_kernel<<<M, 256>>>(Qb, conceptE, EQb);
    edot_kernel<<<M, 256>>>(Kb, conceptE, EKb);
    gram_kernel<<<1, 32>>>(conceptE, Gb);

    // QK[b] = q_sim[b] @ k_sim[b]^T : batched over z
    launch_gemm(Qb, Kb, nullptr, QKb, T, T, D, /*transB*/1, 0,
                Bb, (long long)T * D, (long long)T * D, (long long)T * T);

    sim_attn_kernel<<<dim3(T, Bb), 128>>>(QKb, qa_rel, aq_rel, EQb, EKb, Gb, Pb, Wb);

    // pk[b] = P[b] @ k_sim[b]
    launch_gemm(Pb, Kb, nullptr, PKb, T, D, T, 0, 0,
                Bb, (long long)T * T, (long long)T * D, (long long)T * D);

    final_kernel<<<Bb, 512>>>(PKb, Wb, conceptE, clsw, clsb, out);
}

// round 2
// speedup vs baseline: 3.8865x; 3.8865x over previous
#include <cuda_runtime.h>
#include <cuda_bf16.h>
#include <math.h>

// Problem constants
#define Bb   4
#define T    128
#define D    512
#define Hh   4
#define DK   128
#define NL   4
#define DFF  2048
#define NC   5

#define M2   1024            // merged towers: 2*Bb*T rows
#define ND   (M2*D)          // 524288

// ---------------- scratch ----------------------------------------------------
#define OFF_X   0
#define OFF_Q   (1*ND)
#define OFF_K   (2*ND)
#define OFF_V   (3*ND)
#define OFF_T0  (4*ND)
#define OFF_T1  (5*ND)
#define OFF_H   (6*ND)
#define OFF_FFN (7*ND)              // M2*DFF = 4*ND
#define OFF_S   (11*ND)             // 32*T*T = 524288 = ND
#define OFF_QK  (12*ND)             // 4*T*T = 65536
#define OFF_P   (OFF_QK + 65536)
#define OFF_EQ  (OFF_P + 65536)
#define OFF_EK  (OFF_EQ + 2560)
#define OFF_G   (OFF_EK + 2560)
#define OFF_W   (OFF_G + 32)
#define OFF_PK  (OFF_W + 2560)      // 4*T*D = 262144
#define SCRATCH_TOTAL (OFF_PK + 262144)

__device__ float g_scratch[SCRATCH_TOTAL];

__device__ __forceinline__ float gelu_f(float x) {
    return 0.5f * x * (1.0f + erff(x * 0.7071067811865475f));
}

// ---------------- tf32 helpers ----------------------------------------------
__device__ __forceinline__ unsigned f2tf32(float x) {
    unsigned r;
    asm("cvt.rna.tf32.f32 %0, %1;" : "=r"(r) : "f"(x));
    return r;
}
// split x into hi (tf32-exact) + lo (tf32-rounded residual), both stored as floats
__device__ __forceinline__ void split_tf32(float x, float& hi, float& lo) {
    unsigned h = f2tf32(x);
    hi = __uint_as_float(h);
    float l = x - hi;
    lo = __uint_as_float(f2tf32(l));
}

__device__ __forceinline__ void mma_tf32(float* c, const unsigned* a, const unsigned* b) {
    asm volatile(
        "mma.sync.aligned.m16n8k8.row.col.f32.tf32.tf32.f32 "
        "{%0,%1,%2,%3},{%4,%5,%6,%7},{%8,%9},{%0,%1,%2,%3};"
        : "+f"(c[0]), "+f"(c[1]), "+f"(c[2]), "+f"(c[3])
        : "r"(a[0]), "r"(a[1]), "r"(a[2]), "r"(a[3]), "r"(b[0]), "r"(b[1]));
}

// ---------------- 3xTF32 GEMM ------------------------------------------------
// C = A @ B (+bias)(+gelu). A:[M,K] row-major (leading dim lda).
// B: [K,N] (ldb) or transB: [N,K] (ldb). C: [M,N] (ldc).
// Block tile 128x64, BK=16, 256 threads = 8 warps (4 m x 2 n), warp tile 32x32.
// z-batching: set = z/zPerSet selects (A,W,bias,C) pointer set;
// within set: zz = z%zPerSet, b = zz/nH, h = zz%nH; offsets b*s? + h*h?.
#define GBM 128
#define GBN 64
#define GBK 16
#define PADK 20

__global__ __launch_bounds__(256)
void gemm_tf32(const float* __restrict__ A0, const float* __restrict__ A1, const float* __restrict__ A2,
               const float* __restrict__ W0, const float* __restrict__ W1, const float* __restrict__ W2,
               const float* __restrict__ bias0, const float* __restrict__ bias1, const float* __restrict__ bias2,
               float* __restrict__ C0, float* __restrict__ C1, float* __restrict__ C2,
               int M, int N, int K, int lda, int ldb, int ldc,
               int transB, int act, int nH,
               long long sA, long long hA, long long sB, long long hB,
               long long sC, long long hC, int zPerSet) {
    int z = blockIdx.z;
    int set = z / zPerSet;
    int zz = z % zPerSet;
    int bb = zz / nH, hh = zz % nH;

    const float* A  = (set == 0) ? A0 : (set == 1 ? A1 : A2);
    const float* Bm = (set == 0) ? W0 : (set == 1 ? W1 : W2);
    const float* bias = (set == 0) ? bias0 : (set == 1 ? bias1 : bias2);
    float* C = (set == 0) ? C0 : (set == 1 ? C1 : C2);

    A  += bb * sA + hh * hA;
    Bm += bb * sB + hh * hB;
    C  += bb * sC + hh * hC;

    __shared__ float As[2][GBM][PADK];   // [hi/lo][m][k]
    __shared__ float Bs[2][GBN][PADK];   // [hi/lo][n][k]

    int tid = threadIdx.x;
    int lane = tid & 31, wid = tid >> 5;
    int wm = wid & 3, wn = wid >> 2;          // warp grid 4x2
    int l3 = lane & 3, l2 = lane >> 2;

    int bm = blockIdx.y * GBM;
    int bn = blockIdx.x * GBN;

    float acc[2][4][4];
    #pragma unroll
    for (int i = 0; i < 2; i++)
        #pragma unroll
        for (int j = 0; j < 4; j++)
            #pragma unroll
            for (int q = 0; q < 4; q++) acc[i][j][q] = 0.0f;

    // global load indices
    int ar = tid >> 2;            // 0..63  (A rows, two passes)
    int ak = (tid & 3) * 4;       // k quad
    int bkr = tid >> 4;           // 0..15 (B row k, no-trans)
    int bnc = (tid & 15) * 4;     // n quad
    int tn = tid >> 2;            // 0..63 (trans: n)
    int tk = (tid & 3) * 4;

    #pragma unroll 1
    for (int k0 = 0; k0 < K; k0 += GBK) {
        // ---- global -> regs
        float4 aR0 = *(const float4*)(A + (size_t)(bm + ar) * lda + k0 + ak);
        float4 aR1 = *(const float4*)(A + (size_t)(bm + ar + 64) * lda + k0 + ak);
        float4 bR;
        if (!transB) bR = *(const float4*)(Bm + (size_t)(k0 + bkr) * ldb + bn + bnc);
        else         bR = *(const float4*)(Bm + (size_t)(bn + tn) * ldb + k0 + tk);

        __syncthreads();

        // ---- split & store to smem
        {
            float h0, l0, h1, l1, h2, l2f, h3, l3f;
            split_tf32(aR0.x, h0, l0); split_tf32(aR0.y, h1, l1);
            split_tf32(aR0.z, h2, l2f); split_tf32(aR0.w, h3, l3f);
            *(float4*)&As[0][ar][ak] = make_float4(h0, h1, h2, h3);
            *(float4*)&As[1][ar][ak] = make_float4(l0, l1, l2f, l3f);
            split_tf32(aR1.x, h0, l0); split_tf32(aR1.y, h1, l1);
            split_tf32(aR1.z, h2, l2f); split_tf32(aR1.w, h3, l3f);
            *(float4*)&As[0][ar + 64][ak] = make_float4(h0, h1, h2, h3);
            *(float4*)&As[1][ar + 64][ak] = make_float4(l0, l1, l2f, l3f);
        }
        if (!transB) {
            float h, l;
            split_tf32(bR.x, h, l); Bs[0][bnc + 0][bkr] = h; Bs[1][bnc + 0][bkr] = l;
            split_tf32(bR.y, h, l); Bs[0][bnc + 1][bkr] = h; Bs[1][bnc + 1][bkr] = l;
            split_tf32(bR.z, h, l); Bs[0][bnc + 2][bkr] = h; Bs[1][bnc + 2][bkr] = l;
            split_tf32(bR.w, h, l); Bs[0][bnc + 3][bkr] = h; Bs[1][bnc + 3][bkr] = l;
        } else {
            float h0, l0, h1, l1, h2, l2f, h3, l3f;
            split_tf32(bR.x, h0, l0); split_tf32(bR.y, h1, l1);
            split_tf32(bR.z, h2, l2f); split_tf32(bR.w, h3, l3f);
            *(float4*)&Bs[0][tn][tk] = make_float4(h0, h1, h2, h3);
            *(float4*)&Bs[1][tn][tk] = make_float4(l0, l1, l2f, l3f);
        }
        __syncthreads();

        // ---- compute 2 k-steps of 8
        #pragma unroll
        for (int ks = 0; ks < GBK; ks += 8) {
            unsigned ah[2][4], al[2][4], bh[4][2], bl[4][2];
            #pragma unroll
            for (int i = 0; i < 2; i++) {
                int m0 = wm * 32 + i * 16;
                ah[i][0] = __float_as_uint(As[0][m0 + l2][ks + l3]);
                ah[i][1] = __float_as_uint(As[0][m0 + l2 + 8][ks + l3]);
                ah[i][2] = __float_as_uint(As[0][m0 + l2][ks + l3 + 4]);
                ah[i][3] = __float_as_uint(As[0][m0 + l2 + 8][ks + l3 + 4]);
                al[i][0] = __float_as_uint(As[1][m0 + l2][ks + l3]);
                al[i][1] = __float_as_uint(As[1][m0 + l2 + 8][ks + l3]);
                al[i][2] = __float_as_uint(As[1][m0 + l2][ks + l3 + 4]);
                al[i][3] = __float_as_uint(As[1][m0 + l2 + 8][ks + l3 + 4]);
            }
            #pragma unroll
            for (int j = 0; j < 4; j++) {
                int n0 = wn * 32 + j * 8;
                bh[j][0] = __float_as_uint(Bs[0][n0 + l2][ks + l3]);
                bh[j][1] = __float_as_uint(Bs[0][n0 + l2][ks + l3 + 4]);
                bl[j][0] = __float_as_uint(Bs[1][n0 + l2][ks + l3]);
                bl[j][1] = __float_as_uint(Bs[1][n0 + l2][ks + l3 + 4]);
            }
            #pragma unroll
            for (int i = 0; i < 2; i++)
                #pragma unroll
                for (int j = 0; j < 4; j++) {
                    mma_tf32(acc[i][j], ah[i], bh[j]);
                    mma_tf32(acc[i][j], ah[i], bl[j]);
                    mma_tf32(acc[i][j], al[i], bh[j]);
                }
        }
    }

    // ---- epilogue
    #pragma unroll
    for (int i = 0; i < 2; i++) {
        #pragma unroll
        for (int j = 0; j < 4; j++) {
            int rg = bm + wm * 32 + i * 16 + l2;
            int cg = bn + wn * 32 + j * 8 + 2 * l3;
            float bv0 = bias ? bias[cg] : 0.0f;
            float bv1 = bias ? bias[cg + 1] : 0.0f;
            float v0 = acc[i][j][0] + bv0, v1 = acc[i][j][1] + bv1;
            float v2 = acc[i][j][2] + bv0, v3 = acc[i][j][3] + bv1;
            if (act) { v0 = gelu_f(v0); v1 = gelu_f(v1); v2 = gelu_f(v2); v3 = gelu_f(v3); }
            *(float2*)(C + (size_t)rg * ldc + cg) = make_float2(v0, v1);
            *(float2*)(C + (size_t)(rg + 8) * ldc + cg) = make_float2(v2, v3);
        }
    }
}

// ---------------- warp helpers ----------------------------------------------
__device__ __forceinline__ float warp_sum(float v) {
    #pragma unroll
    for (int o = 16; o > 0; o >>= 1) v += __shfl_xor_sync(0xffffffff, v, o);
    return v;
}
__device__ __forceinline__ float warp_max(float v) {
    #pragma unroll
    for (int o = 16; o > 0; o >>= 1) v = fmaxf(v, __shfl_xor_sync(0xffffffff, v, o));
    return v;
}

// ---------------- LayerNorm kernels (row per block, 128 threads, float4) -----
__global__ void add_pos_ln_kernel(const float* __restrict__ x, const float* __restrict__ pos,
                                  const float* __restrict__ w, const float* __restrict__ b,
                                  float* __restrict__ out) {
    int row = blockIdx.x, tid = threadIdx.x;
    int lane = tid & 31, wd = tid >> 5;
    __shared__ float p1[4], p2[4];

    float4 xv = ((const float4*)(x + (size_t)row * D))[tid];
    float4 pv = ((const float4*)(pos + (size_t)(row % T) * D))[tid];
    float4 v = make_float4(xv.x + pv.x, xv.y + pv.y, xv.z + pv.z, xv.w + pv.w);

    float s = warp_sum(v.x + v.y + v.z + v.w);
    if (lane == 0) p1[wd] = s;
    __syncthreads();
    float mean = (p1[0] + p1[1] + p1[2] + p1[3]) * (1.0f / D);
    float4 d = make_float4(v.x - mean, v.y - mean, v.z - mean, v.w - mean);
    float q = warp_sum(d.x * d.x + d.y * d.y + d.z * d.z + d.w * d.w);
    if (lane == 0) p2[wd] = q;
    __syncthreads();
    float inv = rsqrtf((p2[0] + p2[1] + p2[2] + p2[3]) * (1.0f / D) + 1e-12f);

    float4 wv = ((const float4*)w)[tid];
    float4 bv = ((const float4*)b)[tid];
    ((float4*)(out + (size_t)row * D))[tid] =
        make_float4(wv.x * d.x * inv + bv.x, wv.y * d.y * inv + bv.y,
                    wv.z * d.z * inv + bv.z, wv.w * d.w * inv + bv.w);
}

// x += y (persist); out = LN(x)*w+b  (out may alias x)
__global__ void residual_ln_kernel(float* __restrict__ x, const float* __restrict__ y,
                                   float* __restrict__ out,
                                   const float* __restrict__ w, const float* __restrict__ b) {
    int row = blockIdx.x, tid = threadIdx.x;
    int lane = tid & 31, wd = tid >> 5;
    __shared__ float p1[4], p2[4];

    float4 xv = ((const float4*)(x + (size_t)row * D))[tid];
    float4 yv = ((const float4*)(y + (size_t)row * D))[tid];
    float4 v = make_float4(xv.x + yv.x, xv.y + yv.y, xv.z + yv.z, xv.w + yv.w);
    ((float4*)(x + (size_t)row * D))[tid] = v;

    float s = warp_sum(v.x + v.y + v.z + v.w);
    if (lane == 0) p1[wd] = s;
    __syncthreads();
    float mean = (p1[0] + p1[1] + p1[2] + p1[3]) * (1.0f / D);
    float4 d = make_float4(v.x - mean, v.y - mean, v.z - mean, v.w - mean);
    float q = warp_sum(d.x * d.x + d.y * d.y + d.z * d.z + d.w * d.w);
    if (lane == 0) p2[wd] = q;
    __syncthreads();
    float inv = rsqrtf((p2[0] + p2[1] + p2[2] + p2[3]) * (1.0f / D) + 1e-12f);

    float4 wv = ((const float4*)w)[tid];
    float4 bv = ((const float4*)b)[tid];
    ((float4*)(out + (size_t)row * D))[tid] =
        make_float4(wv.x * d.x * inv + bv.x, wv.y * d.y * inv + bv.y,
                    wv.z * d.z * inv + bv.z, wv.w * d.w * inv + bv.w);
}

// ---------------- attention softmax: rows of 128, warp per row ---------------
__global__ void attn_softmax_kernel(float* __restrict__ S) {
    int row = blockIdx.x * 8 + (threadIdx.x >> 5);
    int lane = threadIdx.x & 31;
    float4* rp = (float4*)(S + (size_t)row * T);
    float4 v = rp[lane];
    const float sc = 0.08838834764831845f;   // 1/sqrt(128)
    v.x *= sc; v.y *= sc; v.z *= sc; v.w *= sc;
    float m = warp_max(fmaxf(fmaxf(v.x, v.y), fmaxf(v.z, v.w)));
    v.x = expf(v.x - m); v.y = expf(v.y - m); v.z = expf(v.z - m); v.w = expf(v.w - m);
    float s = warp_sum(v.x + v.y + v.z + v.w);
    float inv = 1.0f / s;
    v.x *= inv; v.y *= inv; v.z *= inv; v.w *= inv;
    rp[lane] = v;
}

// ---------------- sim head helpers ------------------------------------------
__global__ void edot_kernel(const float* __restrict__ X, const float* __restrict__ E,
                            float* __restrict__ out) {
    int row = blockIdx.x;
    int tid = threadIdx.x;
    __shared__ float red[NC * 256];
    float acc[NC] = {};
    for (int d = tid; d < D; d += 256) {
        float x = X[(size_t)row * D + d];
        #pragma unroll
        for (int c = 0; c < NC; c++) acc[c] += x * E[(size_t)c * D + d];
    }
    #pragma unroll
    for (int c = 0; c < NC; c++) red[c * 256 + tid] = acc[c];
    __syncthreads();
    for (int off = 128; off > 0; off >>= 1) {
        if (tid < off) {
            #pragma unroll
            for (int c = 0; c < NC; c++) red[c * 256 + tid] += red[c * 256 + tid + off];
        }
        __syncthreads();
    }
    if (tid < NC) out[(size_t)row * NC + tid] = red[tid * 256];
}

__global__ void gram_kernel(const float* __restrict__ E, float* __restrict__ G) {
    int i = threadIdx.x;
    if (i < NC * NC) {
        int c = i / NC, c2 = i % NC;
        float s = 0.0f;
        for (int d = 0; d < D; d++) s += E[(size_t)c * D + d] * E[(size_t)c2 * D + d];
        G[i] = s;
    }
}

__global__ void sim_attn_kernel(const float* __restrict__ QK, const float* __restrict__ qa,
                                const float* __restrict__ aq, const float* __restrict__ Eq,
                                const float* __restrict__ Ek, const float* __restrict__ G,
                                float* __restrict__ P, float* __restrict__ Wout) {
    int t = blockIdx.x, b = blockIdx.y;
    int s = threadIdx.x;                 // 128 threads
    int lane = s & 31, wd = s >> 5;
    __shared__ float g[NC * NC];
    __shared__ float part[4];
    __shared__ float pv[T];
    if (s < NC * NC) g[s] = G[s];
    __syncthreads();

    float f1[NC], f2[NC];
    const float* r1 = qa + (((size_t)b * T + t) * T + s) * NC;
    const float* r2 = aq + (((size_t)b * T + s) * T + t) * NC;
    #pragma unroll
    for (int c = 0; c < NC; c++) { f1[c] = r1[c]; f2[c] = r2[c]; }

    float sc = QK[((size_t)b * T + t) * T + s];
    const float* eq = Eq + ((size_t)b * T + t) * NC;
    const float* ek = Ek + ((size_t)b * T + s) * NC;
    #pragma unroll
    for (int c = 0; c < NC; c++) sc += f1[c] * ek[c] + f2[c] * eq[c];
    #pragma unroll
    for (int c = 0; c < NC; c++)
        #pragma unroll
        for (int c2 = 0; c2 < NC; c2++)
            sc += f1[c] * g[c * NC + c2] * f2[c2];

    // softmax #1 (cross-warp via shared)
    float m = warp_max(sc);
    if (lane == 0) part[wd] = m;
    __syncthreads();
    float m1 = fmaxf(fmaxf(part[0], part[1]), fmaxf(part[2], part[3]));
    float e1 = expf(sc - m1);
    float ssum = warp_sum(e1);
    if (lane == 0) part[wd] = ssum;
    __syncthreads();
    float p = e1 / (part[0] + part[1] + part[2] + part[3]);

    // sharpening softmax(1000*p)
    float l = 1000.0f * p;
    m = warp_max(l);
    __syncthreads();
    if (lane == 0) part[wd] = m;
    __syncthreads();
    float m2 = fmaxf(fmaxf(part[0], part[1]), fmaxf(part[2], part[3]));
    float e2 = expf(l - m2);
    ssum = warp_sum(e2);
    __syncthreads();
    if (lane == 0) part[wd] = ssum;
    __syncthreads();
    float p2 = e2 / (part[0] + part[1] + part[2] + part[3]);
    p2 = fminf(fmaxf(p2, 0.0f), 1.0f);

    P[((size_t)b * T + t) * T + s] = p2;
    pv[s] = p2;
    __syncthreads();

    #pragma unroll
    for (int c = 0; c < NC; c++) {
        float v = warp_sum(pv[s] * f2[c]);
        __syncthreads();
        if (lane == 0) part[wd] = v;
        __syncthreads();
        if (s == 0) Wout[((size_t)b * T + t) * NC + c] = part[0] + part[1] + part[2] + part[3];
    }
}

__global__ void final_kernel(const float* __restrict__ pk, const float* __restrict__ Wm,
                             const float* __restrict__ E, const float* __restrict__ clsw,
                             const float* __restrict__ clsb, float* __restrict__ out) {
    int b = blockIdx.x;
    int d = threadIdx.x;                 // 512 threads
    __shared__ float wm[NC];
    __shared__ float red[512];

    if (d < NC) {
        float s = 0.0f;
        for (int t = 0; t < T; t++) s += Wm[((size_t)b * T + t) * NC + d];
        wm[d] = s * (1.0f / T);
    }
    __syncthreads();

    float s = 0.0f;
    for (int t = 0; t < T; t++) s += pk[((size_t)b * T + t) * D + d];
    s *= (1.0f / T);
    #pragma unroll
    for (int c = 0; c < NC; c++) s += wm[c] * E[(size_t)c * D + d];

    for (int j = 0; j < 3; j++) {
        red[d] = s * clsw[(size_t)d * 3 + j];
        __syncthreads();
        for (int off = 256; off > 0; off >>= 1) { if (d < off) red[d] += red[d + off]; __syncthreads(); }
        if (d == 0) out[b * 3 + j] = red[0] + clsb[j];
        __syncthreads();
    }
}

// ---------------- host orchestration ----------------------------------------
static inline void g_launch(const float* A0, const float* A1, const float* A2,
                            const float* W0, const float* W1, const float* W2,
                            const float* b0, const float* b1, const float* b2,
                            float* C0, float* C1, float* C2,
                            int M, int N, int K, int lda, int ldb, int ldc,
                            int transB, int act, int nH,
                            long long sA, long long hA, long long sB, long long hB,
                            long long sC, long long hC, int zPerSet, int nz) {
    dim3 grid(N / GBN, M / GBM, nz);
    gemm_tf32<<<grid, 256>>>(A0, A1, A2, W0, W1, W2, b0, b1, b2, C0, C1, C2,
                             M, N, K, lda, ldb, ldc, transB, act, nH,
                             sA, hA, sB, hB, sC, hC, zPerSet);
}

extern "C" void kernel_launch(void* const* d_in, const int* in_sizes, int n_in,
                              void* d_out, int out_size) {
    const float* q_emb   = (const float*)d_in[0];
    const float* a_emb   = (const float*)d_in[1];
    const float* qa_rel  = (const float*)d_in[2];
    const float* aq_rel  = (const float*)d_in[3];
    const float* conceptE= (const float*)d_in[4];
    const float* pos_emb = (const float*)d_in[5];
    const float* pe_w    = (const float*)d_in[6];
    const float* pe_b    = (const float*)d_in[7];
    const float* Wq      = (const float*)d_in[8];
    const float* bq      = (const float*)d_in[9];
    const float* Wk      = (const float*)d_in[10];
    const float* bk      = (const float*)d_in[11];
    const float* Wv      = (const float*)d_in[12];
    const float* bv      = (const float*)d_in[13];
    const float* Wo      = (const float*)d_in[14];
    const float* bo      = (const float*)d_in[15];
    const float* ff1w    = (const float*)d_in[16];
    const float* ff1b    = (const float*)d_in[17];
    const float* ff2w    = (const float*)d_in[18];
    const float* ff2b    = (const float*)d_in[19];
    const float* lninw   = (const float*)d_in[20];
    const float* lninb   = (const float*)d_in[21];
    const float* lnoutw  = (const float*)d_in[22];
    const float* lnoutb  = (const float*)d_in[23];
    const float* simWq   = (const float*)d_in[24];
    const float* simbq   = (const float*)d_in[25];
    const float* simWk   = (const float*)d_in[26];
    const float* simbk   = (const float*)d_in[27];
    const float* clsw    = (const float*)d_in[28];
    const float* clsb    = (const float*)d_in[29];
    float* out = (float*)d_out;

    float* base = nullptr;
    cudaGetSymbolAddress((void**)&base, g_scratch);

    float* X   = base + OFF_X;        // merged towers [1024, 512]; QE=rows0..511, AE=512..1023
    float* Qb  = base + OFF_Q;
    float* Kb  = base + OFF_K;
    float* Vb  = base + OFF_V;
    float* T0  = base + OFF_T0;
    float* T1b = base + OFF_T1;
    float* Hb  = base + OFF_H;
    float* FFN = base + OFF_FFN;
    float* Sb  = base + OFF_S;        // attn scores [32][128][128]
    float* QKb = base + OFF_QK;
    float* Pb  = base + OFF_P;
    float* EQb = base + OFF_EQ;
    float* EKb = base + OFF_EK;
    float* Gb  = base + OFF_G;
    float* Wb  = base + OFF_W;
    float* PKb = base + OFF_PK;

    // pos + LN for both towers (q_emb then a_emb -> X)
    add_pos_ln_kernel<<<M2 / 2, 128>>>(q_emb, pos_emb, pe_w, pe_b, X);
    add_pos_ln_kernel<<<M2 / 2, 128>>>(a_emb, pos_emb, pe_w, pe_b, X + (size_t)(M2 / 2) * D);

    for (int i = 0; i < NL; i++) {
        const float* wq = Wq + (size_t)i * D * D;
        const float* wk = Wk + (size_t)i * D * D;
        const float* wv = Wv + (size_t)i * D * D;
        const float* wo = Wo + (size_t)i * D * D;

        // fused QKV: 3 sets, one launch
        g_launch(X, X, X, wq, wk, wv,
                 bq + (size_t)i * D, bk + (size_t)i * D, bv + (size_t)i * D,
                 Qb, Kb, Vb,
                 M2, D, D, D, D, D, 0, 0, 1, 0, 0, 0, 0, 0, 0, 1, 3);

        // scores: z = b'*4+h (b' covers both towers), S = Q @ K^T
        g_launch(Qb, 0, 0, Kb, 0, 0, 0, 0, 0, Sb, 0, 0,
                 T, T, DK, D, D, T, 1, 0, Hh,
                 (long long)T * D, DK, (long long)T * D, DK,
                 (long long)Hh * T * T, (long long)T * T, 32, 32);

        attn_softmax_kernel<<<(32 * T) / 8, 256>>>(Sb);

        // O-heads: T0 = P @ V
        g_launch(Sb, 0, 0, Vb, 0, 0, 0, 0, 0, T0, 0, 0,
                 T, DK, T, T, D, D, 0, 0, Hh,
                 (long long)Hh * T * T, (long long)T * T, (long long)T * D, DK,
                 (long long)T * D, DK, 32, 32);

        // output projection
        g_launch(T0, 0, 0, wo, 0, 0, bo + (size_t)i * D, 0, 0, T1b, 0, 0,
                 M2, D, D, D, D, D, 0, 0, 1, 0, 0, 0, 0, 0, 0, 1, 1);

        residual_ln_kernel<<<M2, 128>>>(X, T1b, Hb, lninw + (size_t)i * D, lninb + (size_t)i * D);

        g_launch(Hb, 0, 0, ff1w + (size_t)i * D * DFF, 0, 0, ff1b + (size_t)i * DFF, 0, 0, FFN, 0, 0,
                 M2, DFF, D, D, DFF, DFF, 0, 1, 1, 0, 0, 0, 0, 0, 0, 1, 1);
        g_launch(FFN, 0, 0, ff2w + (size_t)i * DFF * D, 0, 0, ff2b + (size_t)i * D, 0, 0, T1b, 0, 0,
                 M2, D, DFF, DFF, D, D, 0, 0, 1, 0, 0, 0, 0, 0, 0, 1, 1);

        residual_ln_kernel<<<M2, 128>>>(X, T1b, X, lnoutw + (size_t)i * D, lnoutb + (size_t)i * D);
    }

    // --- sim head (factored; hL/hR never materialized) ---
    // q_sim (from QE rows) and k_sim (from AE rows), one launch, 2 sets
    g_launch(X, X + (size_t)(M2 / 2) * D, 0, simWq, simWk, 0, simbq, simbk, 0, Qb, Kb, 0,
             M2 / 2, D, D, D, D, D, 0, 0, 1, 0, 0, 0, 0, 0, 0, 1, 2);

    edot_kernel<<<M2 / 2, 256>>>(Qb, conceptE, EQb);
    edot_kernel<<<M2 / 2, 256>>>(Kb, conceptE, EKb);
    gram_kernel<<<1, 32>>>(conceptE, Gb);

    // QK[b] = q_sim[b] @ k_sim[b]^T
    g_launch(Qb, 0, 0, Kb, 0, 0, 0, 0, 0, QKb, 0, 0,
             T, T, D, D, D, T, 1, 0, 1,
             (long long)T * D, 0, (long long)T * D, 0, (long long)T * T, 0, 4, 4);

    sim_attn_kernel<<<dim3(T, Bb), 128>>>(QKb, qa_rel, aq_rel, EQb, EKb, Gb, Pb, Wb);

    // pk[b] = P[b] @ k_sim[b]
    g_launch(Pb, 0, 0, Kb, 0, 0, 0, 0, 0, PKb, 0, 0,
             T, D, T, T, D, D, 0, 0, 1,
             (long long)T * T, 0, (long long)T * D, 0, (long long)T * D, 0, 4, 4);

    final_kernel<<<Bb, 512>>>(PKb, Wb, conceptE, clsw, clsb, out);
}

// round 3
// speedup vs baseline: 6.5104x; 1.6751x over previous
#include <cuda_runtime.h>
#include <cuda_bf16.h>
#include <math.h>

// Problem constants
#define Bb   4
#define T    128
#define D    512
#define Hh   4
#define DK   128
#define NL   4
#define DFF  2048
#define NC   5

#define M2   1024            // merged towers: 2*Bb*T rows
#define ND   (M2*D)          // 524288

// ---------------- scratch ----------------------------------------------------
#define OFF_X   0
#define OFF_Q   (1*ND)
#define OFF_K   (2*ND)
#define OFF_V   (3*ND)
#define OFF_T0  (4*ND)
#define OFF_T1  (5*ND)
#define OFF_H   (6*ND)
#define OFF_FFN (7*ND)              // M2*DFF = 4*ND
#define OFF_QK  (11*ND)
#define OFF_P   (OFF_QK + 65536)
#define OFF_EQ  (OFF_P + 65536)
#define OFF_EK  (OFF_EQ + 2560)
#define OFF_G   (OFF_EK + 2560)
#define OFF_W   (OFF_G + 32)
#define OFF_PK  (OFF_W + 2560)      // 4*T*D = 262144
#define SCRATCH_TOTAL (OFF_PK + 262144)

__device__ float g_scratch[SCRATCH_TOTAL];

__device__ __forceinline__ float gelu_f(float x) {
    return 0.5f * x * (1.0f + erff(x * 0.7071067811865475f));
}

// ---------------- tf32 / mma / cp.async helpers ------------------------------
__device__ __forceinline__ unsigned f2tf32(float x) {
    unsigned r;
    asm("cvt.rna.tf32.f32 %0, %1;" : "=r"(r) : "f"(x));
    return r;
}
__device__ __forceinline__ void split2(float x, unsigned& hi, unsigned& lo) {
    hi = f2tf32(x);
    lo = f2tf32(x - __uint_as_float(hi));
}
__device__ __forceinline__ void mma_tf32(float* c, const unsigned* a, const unsigned* b) {
    asm volatile(
        "mma.sync.aligned.m16n8k8.row.col.f32.tf32.tf32.f32 "
        "{%0,%1,%2,%3},{%4,%5,%6,%7},{%8,%9},{%0,%1,%2,%3};"
        : "+f"(c[0]), "+f"(c[1]), "+f"(c[2]), "+f"(c[3])
        : "r"(a[0]), "r"(a[1]), "r"(a[2]), "r"(a[3]), "r"(b[0]), "r"(b[1]));
}
// 3xTF32: (ah+al)*(bh+bl) ~= ah*bh + ah*bl + al*bh
__device__ __forceinline__ void mma3(float* c, const unsigned* ah, const unsigned* al,
                                     const unsigned* bh, const unsigned* bl) {
    mma_tf32(c, ah, bh);
    mma_tf32(c, ah, bl);
    mma_tf32(c, al, bh);
}
__device__ __forceinline__ void cp16(void* s, const void* g) {
    unsigned sa = (unsigned)__cvta_generic_to_shared(s);
    asm volatile("cp.async.cg.shared.global [%0], [%1], 16;\n" :: "r"(sa), "l"(g) : "memory");
}
#define CP_COMMIT() asm volatile("cp.async.commit_group;\n" ::: "memory")
#define CP_WAIT(n)  asm volatile("cp.async.wait_group %0;\n" :: "n"(n) : "memory")

// ---------------- pipelined 3xTF32 GEMM, 64x64 tile, 3-stage cp.async --------
// C = A @ B (+bias)(+gelu). A:[M,K] (lda). B: [K,N](ldb) or TRANSB [N,K](ldb).
// 256 threads = 8 warps; warp grid 2(m) x 4(n); warp tile 32x16.
#define PADK 20
#define PADN 72

template<int TRANSB>
__global__ __launch_bounds__(256)
void gemm_tf32(const float* __restrict__ A0, const float* __restrict__ A1, const float* __restrict__ A2,
               const float* __restrict__ W0, const float* __restrict__ W1, const float* __restrict__ W2,
               const float* __restrict__ bias0, const float* __restrict__ bias1, const float* __restrict__ bias2,
               float* __restrict__ C0, float* __restrict__ C1, float* __restrict__ C2,
               int M, int N, int K, int lda, int ldb, int ldc,
               int act, int nH,
               long long sA, long long hA, long long sB, long long hB,
               long long sC, long long hC, int zPerSet) {
    int z = blockIdx.z;
    int set = z / zPerSet;
    int zz = z % zPerSet;
    int bb = zz / nH, hh = zz % nH;

    const float* A  = (set == 0) ? A0 : (set == 1 ? A1 : A2);
    const float* Bm = (set == 0) ? W0 : (set == 1 ? W1 : W2);
    const float* bias = (set == 0) ? bias0 : (set == 1 ? bias1 : bias2);
    float* C = (set == 0) ? C0 : (set == 1 ? C1 : C2);
    A  += bb * sA + hh * hA;
    Bm += bb * sB + hh * hB;
    C  += bb * sC + hh * hC;

    __shared__ float As[3][64][PADK];
    constexpr int BR = TRANSB ? 64 : 16;
    constexpr int BC = TRANSB ? PADK : PADN;
    __shared__ float Bs[3][BR][BC];

    int tid = threadIdx.x;
    int lane = tid & 31, wid = tid >> 5;
    int wm = wid & 1, wn = wid >> 1;
    int l3 = lane & 3, l2 = lane >> 2;

    int bm = blockIdx.y * 64;
    int bn = blockIdx.x * 64;

    // load indices
    int ar = tid >> 2, ak = (tid & 3) * 4;        // A: 64x16
    int tbr = tid >> 2, tbk = (tid & 3) * 4;      // B trans: 64x16
    int nbr = tid >> 4, nbc = (tid & 15) * 4;     // B non-trans: 16x64

    float acc[2][2][4] = {};

    int nk = K / 16;

    // prologue: stages 0,1
    #pragma unroll
    for (int p = 0; p < 2; p++) {
        int k0 = p * 16;
        cp16(&As[p][ar][ak], A + (size_t)(bm + ar) * lda + k0 + ak);
        if (TRANSB) cp16(&Bs[p][tbr][tbk], Bm + (size_t)(bn + tbr) * ldb + k0 + tbk);
        else        cp16(&Bs[p][nbr][nbc], Bm + (size_t)(k0 + nbr) * ldb + bn + nbc);
        CP_COMMIT();
    }

    for (int kt = 0; kt < nk; kt++) {
        CP_WAIT(1);
        __syncthreads();
        int st = kt % 3;
        if (kt + 2 < nk) {
            int ns = (kt + 2) % 3;
            int k0 = (kt + 2) * 16;
            cp16(&As[ns][ar][ak], A + (size_t)(bm + ar) * lda + k0 + ak);
            if (TRANSB) cp16(&Bs[ns][tbr][tbk], Bm + (size_t)(bn + tbr) * ldb + k0 + tbk);
            else        cp16(&Bs[ns][nbr][nbc], Bm + (size_t)(k0 + nbr) * ldb + bn + nbc);
        }
        CP_COMMIT();

        #pragma unroll
        for (int ks = 0; ks < 16; ks += 8) {
            unsigned ah[2][4], al[2][4], bh[2][2], bl[2][2];
            #pragma unroll
            for (int i = 0; i < 2; i++) {
                int m0 = wm * 32 + i * 16;
                split2(As[st][m0 + l2][ks + l3],         ah[i][0], al[i][0]);
                split2(As[st][m0 + l2 + 8][ks + l3],     ah[i][1], al[i][1]);
                split2(As[st][m0 + l2][ks + l3 + 4],     ah[i][2], al[i][2]);
                split2(As[st][m0 + l2 + 8][ks + l3 + 4], ah[i][3], al[i][3]);
            }
            #pragma unroll
            for (int j = 0; j < 2; j++) {
                int n0 = wn * 16 + j * 8;
                if (TRANSB) {
                    split2(Bs[st][n0 + l2][ks + l3],     bh[j][0], bl[j][0]);
                    split2(Bs[st][n0 + l2][ks + l3 + 4], bh[j][1], bl[j][1]);
                } else {
                    split2(Bs[st][ks + l3][n0 + l2],     bh[j][0], bl[j][0]);
                    split2(Bs[st][ks + l3 + 4][n0 + l2], bh[j][1], bl[j][1]);
                }
            }
            #pragma unroll
            for (int i = 0; i < 2; i++)
                #pragma unroll
                for (int j = 0; j < 2; j++)
                    mma3(acc[i][j], ah[i], al[i], bh[j], bl[j]);
        }
    }

    // epilogue
    #pragma unroll
    for (int i = 0; i < 2; i++) {
        #pragma unroll
        for (int j = 0; j < 2; j++) {
            int rg = bm + wm * 32 + i * 16 + l2;
            int cg = bn + wn * 16 + j * 8 + 2 * l3;
            float bv0 = bias ? bias[cg] : 0.0f;
            float bv1 = bias ? bias[cg + 1] : 0.0f;
            float v0 = acc[i][j][0] + bv0, v1 = acc[i][j][1] + bv1;
            float v2 = acc[i][j][2] + bv0, v3 = acc[i][j][3] + bv1;
            if (act) { v0 = gelu_f(v0); v1 = gelu_f(v1); v2 = gelu_f(v2); v3 = gelu_f(v3); }
            *(float2*)(C + (size_t)rg * ldc + cg) = make_float2(v0, v1);
            *(float2*)(C + (size_t)(rg + 8) * ldc + cg) = make_float2(v2, v3);
        }
    }
}

// ---------------- fused attention: S=QK^T, softmax, O=PV ---------------------
// grid: (2 row-halves, 32 (b',h)); 256 threads = 8 warps, warp grid 2(m) x 4(n).
// Q tile 64x128 in Pbuf (reused for P); K tile 128x128 in Kbuf (reused for V).
#define APAD 132
__global__ __launch_bounds__(256)
void fused_attn(const float* __restrict__ Q, const float* __restrict__ K,
                const float* __restrict__ V, float* __restrict__ O) {
    extern __shared__ float dyn[];
    float* Pbuf = dyn;                  // [64][APAD]
    float* Kbuf = dyn + 64 * APAD;      // [128][APAD]
    __shared__ float redM[64][4];
    __shared__ float redS[64][4];

    int bz = blockIdx.y;
    int bb = bz >> 2, h = bz & 3;
    int qbase = blockIdx.x * 64;

    int tid = threadIdx.x;
    int lane = tid & 31, wid = tid >> 5;
    int wm = wid & 1, wn = wid >> 1;       // warp tile 32(m) x 32(n)
    int l3 = lane & 3, l2 = lane >> 2;

    const float* Qg = Q + ((size_t)bb * T + qbase) * D + h * DK;
    const float* Kg = K + ((size_t)bb * T) * D + h * DK;
    const float* Vg = V + ((size_t)bb * T) * D + h * DK;

    // load Q (64x128) and K (128x128)
    #pragma unroll
    for (int t = 0; t < 8; t++) {
        int idx = tid + t * 256;            // quad index over 64*32
        int r = idx >> 5, c = (idx & 31) * 4;
        cp16(&Pbuf[r * APAD + c], Qg + (size_t)r * D + c);
    }
    CP_COMMIT();
    #pragma unroll
    for (int t = 0; t < 16; t++) {
        int idx = tid + t * 256;
        int r = idx >> 5, c = (idx & 31) * 4;
        cp16(&Kbuf[r * APAD + c], Kg + (size_t)r * D + c);
    }
    CP_COMMIT();
    CP_WAIT(0);
    __syncthreads();

    // ---- phase 1: S = Q @ K^T  (M=64, N=128, K=128)
    float acc[2][4][4] = {};
    #pragma unroll 4
    for (int ks = 0; ks < DK; ks += 8) {
        unsigned ah[2][4], al[2][4], bh[4][2], bl[4][2];
        #pragma unroll
        for (int i = 0; i < 2; i++) {
            int m0 = wm * 32 + i * 16;
            split2(Pbuf[(m0 + l2) * APAD + ks + l3],         ah[i][0], al[i][0]);
            split2(Pbuf[(m0 + l2 + 8) * APAD + ks + l3],     ah[i][1], al[i][1]);
            split2(Pbuf[(m0 + l2) * APAD + ks + l3 + 4],     ah[i][2], al[i][2]);
            split2(Pbuf[(m0 + l2 + 8) * APAD + ks + l3 + 4], ah[i][3], al[i][3]);
        }
        #pragma unroll
        for (int j = 0; j < 4; j++) {
            int n0 = wn * 32 + j * 8;
            split2(Kbuf[(n0 + l2) * APAD + ks + l3],     bh[j][0], bl[j][0]);
            split2(Kbuf[(n0 + l2) * APAD + ks + l3 + 4], bh[j][1], bl[j][1]);
        }
        #pragma unroll
        for (int i = 0; i < 2; i++)
            #pragma unroll
            for (int j = 0; j < 4; j++)
                mma3(acc[i][j], ah[i], al[i], bh[j], bl[j]);
    }
    __syncthreads();   // Q/K reads done

    // issue V load into Kbuf (overlaps softmax)
    #pragma unroll
    for (int t = 0; t < 16; t++) {
        int idx = tid + t * 256;
        int r = idx >> 5, c = (idx & 31) * 4;
        cp16(&Kbuf[r * APAD + c], Vg + (size_t)r * D + c);
    }
    CP_COMMIT();

    // ---- softmax over rows (scale, max, exp, sum, normalize)
    const float sc = 0.08838834764831845f;     // 1/sqrt(128)
    #pragma unroll
    for (int i = 0; i < 2; i++)
        #pragma unroll
        for (int j = 0; j < 4; j++)
            #pragma unroll
            for (int q = 0; q < 4; q++) acc[i][j][q] *= sc;

    #pragma unroll
    for (int i = 0; i < 2; i++) {
        #pragma unroll
        for (int hf = 0; hf < 2; hf++) {
            int row = wm * 32 + i * 16 + l2 + hf * 8;
            float m = -1e30f;
            #pragma unroll
            for (int j = 0; j < 4; j++) m = fmaxf(m, fmaxf(acc[i][j][2 * hf], acc[i][j][2 * hf + 1]));
            m = fmaxf(m, __shfl_xor_sync(0xffffffff, m, 1));
            m = fmaxf(m, __shfl_xor_sync(0xffffffff, m, 2));
            if (l3 == 0) redM[row][wn] = m;
        }
    }
    __syncthreads();
    float rsum[2][2];
    #pragma unroll
    for (int i = 0; i < 2; i++) {
        #pragma unroll
        for (int hf = 0; hf < 2; hf++) {
            int row = wm * 32 + i * 16 + l2 + hf * 8;
            float m = fmaxf(fmaxf(redM[row][0], redM[row][1]), fmaxf(redM[row][2], redM[row][3]));
            float s = 0.0f;
            #pragma unroll
            for (int j = 0; j < 4; j++) {
                acc[i][j][2 * hf]     = expf(acc[i][j][2 * hf] - m);
                acc[i][j][2 * hf + 1] = expf(acc[i][j][2 * hf + 1] - m);
                s += acc[i][j][2 * hf] + acc[i][j][2 * hf + 1];
            }
            s += __shfl_xor_sync(0xffffffff, s, 1);
            s += __shfl_xor_sync(0xffffffff, s, 2);
            if (l3 == 0) redS[row][wn] = s;
            rsum[i][hf] = 0.0f;
        }
    }
    __syncthreads();
    // normalize and write P into Pbuf
    #pragma unroll
    for (int i = 0; i < 2; i++) {
        #pragma unroll
        for (int hf = 0; hf < 2; hf++) {
            int row = wm * 32 + i * 16 + l2 + hf * 8;
            float inv = 1.0f / (redS[row][0] + redS[row][1] + redS[row][2] + redS[row][3]);
            rsum[i][hf] = inv;
            #pragma unroll
            for (int j = 0; j < 4; j++) {
                int col = wn * 32 + j * 8 + 2 * l3;
                Pbuf[row * APAD + col]     = acc[i][j][2 * hf] * inv;
                Pbuf[row * APAD + col + 1] = acc[i][j][2 * hf + 1] * inv;
            }
        }
    }
    CP_WAIT(0);
    __syncthreads();   // P written, V arrived

    // ---- phase 2: O = P @ V  (M=64, N=128(dk), K=128(keys))
    float out[2][4][4] = {};
    #pragma unroll 4
    for (int ks = 0; ks < T; ks += 8) {
        unsigned ah[2][4], al[2][4], bh[4][2], bl[4][2];
        #pragma unroll
        for (int i = 0; i < 2; i++) {
            int m0 = wm * 32 + i * 16;
            split2(Pbuf[(m0 + l2) * APAD + ks + l3],         ah[i][0], al[i][0]);
            split2(Pbuf[(m0 + l2 + 8) * APAD + ks + l3],     ah[i][1], al[i][1]);
            split2(Pbuf[(m0 + l2) * APAD + ks + l3 + 4],     ah[i][2], al[i][2]);
            split2(Pbuf[(m0 + l2 + 8) * APAD + ks + l3 + 4], ah[i][3], al[i][3]);
        }
        #pragma unroll
        for (int j = 0; j < 4; j++) {
            int n0 = wn * 32 + j * 8;
            split2(Kbuf[(ks + l3) * APAD + n0 + l2],     bh[j][0], bl[j][0]);
            split2(Kbuf[(ks + l3 + 4) * APAD + n0 + l2], bh[j][1], bl[j][1]);
        }
        #pragma unroll
        for (int i = 0; i < 2; i++)
            #pragma unroll
            for (int j = 0; j < 4; j++)
                mma3(out[i][j], ah[i], al[i], bh[j], bl[j]);
    }

    // epilogue: O rows (bb*T + qbase + row), cols h*DK + col
    float* Og = O + ((size_t)bb * T + qbase) * D + h * DK;
    #pragma unroll
    for (int i = 0; i < 2; i++) {
        #pragma unroll
        for (int j = 0; j < 4; j++) {
            int r = wm * 32 + i * 16 + l2;
            int c = wn * 32 + j * 8 + 2 * l3;
            *(float2*)(Og + (size_t)r * D + c) = make_float2(out[i][j][0], out[i][j][1]);
            *(float2*)(Og + (size_t)(r + 8) * D + c) = make_float2(out[i][j][2], out[i][j][3]);
        }
    }
}

// ---------------- warp helpers ----------------------------------------------
__device__ __forceinline__ float warp_sum(float v) {
    #pragma unroll
    for (int o = 16; o > 0; o >>= 1) v += __shfl_xor_sync(0xffffffff, v, o);
    return v;
}
__device__ __forceinline__ float warp_max(float v) {
    #pragma unroll
    for (int o = 16; o > 0; o >>= 1) v = fmaxf(v, __shfl_xor_sync(0xffffffff, v, o));
    return v;
}

// ---------------- LayerNorm kernels ------------------------------------------
__global__ void add_pos_ln_kernel(const float* __restrict__ x, const float* __restrict__ pos,
                                  const float* __restrict__ w, const float* __restrict__ b,
                                  float* __restrict__ out) {
    int row = blockIdx.x, tid = threadIdx.x;
    int lane = tid & 31, wd = tid >> 5;
    __shared__ float p1[4], p2[4];

    float4 xv = ((const float4*)(x + (size_t)row * D))[tid];
    float4 pv = ((const float4*)(pos + (size_t)(row % T) * D))[tid];
    float4 v = make_float4(xv.x + pv.x, xv.y + pv.y, xv.z + pv.z, xv.w + pv.w);

    float s = warp_sum(v.x + v.y + v.z + v.w);
    if (lane == 0) p1[wd] = s;
    __syncthreads();
    float mean = (p1[0] + p1[1] + p1[2] + p1[3]) * (1.0f / D);
    float4 d = make_float4(v.x - mean, v.y - mean, v.z - mean, v.w - mean);
    float q = warp_sum(d.x * d.x + d.y * d.y + d.z * d.z + d.w * d.w);
    if (lane == 0) p2[wd] = q;
    __syncthreads();
    float inv = rsqrtf((p2[0] + p2[1] + p2[2] + p2[3]) * (1.0f / D) + 1e-12f);

    float4 wv = ((const float4*)w)[tid];
    float4 bv = ((const float4*)b)[tid];
    ((float4*)(out + (size_t)row * D))[tid] =
        make_float4(wv.x * d.x * inv + bv.x, wv.y * d.y * inv + bv.y,
                    wv.z * d.z * inv + bv.z, wv.w * d.w * inv + bv.w);
}

__global__ void residual_ln_kernel(float* __restrict__ x, const float* __restrict__ y,
                                   float* __restrict__ out,
                                   const float* __restrict__ w, const float* __restrict__ b) {
    int row = blockIdx.x, tid = threadIdx.x;
    int lane = tid & 31, wd = tid >> 5;
    __shared__ float p1[4], p2[4];

    float4 xv = ((const float4*)(x + (size_t)row * D))[tid];
    float4 yv = ((const float4*)(y + (size_t)row * D))[tid];
    float4 v = make_float4(xv.x + yv.x, xv.y + yv.y, xv.z + yv.z, xv.w + yv.w);
    ((float4*)(x + (size_t)row * D))[tid] = v;

    float s = warp_sum(v.x + v.y + v.z + v.w);
    if (lane == 0) p1[wd] = s;
    __syncthreads();
    float mean = (p1[0] + p1[1] + p1[2] + p1[3]) * (1.0f / D);
    float4 d = make_float4(v.x - mean, v.y - mean, v.z - mean, v.w - mean);
    float q = warp_sum(d.x * d.x + d.y * d.y + d.z * d.z + d.w * d.w);
    if (lane == 0) p2[wd] = q;
    __syncthreads();
    float inv = rsqrtf((p2[0] + p2[1] + p2[2] + p2[3]) * (1.0f / D) + 1e-12f);

    float4 wv = ((const float4*)w)[tid];
    float4 bv = ((const float4*)b)[tid];
    ((float4*)(out + (size_t)row * D))[tid] =
        make_float4(wv.x * d.x * inv + bv.x, wv.y * d.y * inv + bv.y,
                    wv.z * d.z * inv + bv.z, wv.w * d.w * inv + bv.w);
}

// ---------------- sim head helpers ------------------------------------------
__global__ void edot_kernel(const float* __restrict__ X, const float* __restrict__ E,
                            float* __restrict__ out) {
    int row = blockIdx.x;
    int tid = threadIdx.x;
    __shared__ float red[NC * 256];
    float acc[NC] = {};
    for (int d = tid; d < D; d += 256) {
        float x = X[(size_t)row * D + d];
        #pragma unroll
        for (int c = 0; c < NC; c++) acc[c] += x * E[(size_t)c * D + d];
    }
    #pragma unroll
    for (int c = 0; c < NC; c++) red[c * 256 + tid] = acc[c];
    __syncthreads();
    for (int off = 128; off > 0; off >>= 1) {
        if (tid < off) {
            #pragma unroll
            for (int c = 0; c < NC; c++) red[c * 256 + tid] += red[c * 256 + tid + off];
        }
        __syncthreads();
    }
    if (tid < NC) out[(size_t)row * NC + tid] = red[tid * 256];
}

__global__ void gram_kernel(const float* __restrict__ E, float* __restrict__ G) {
    int i = threadIdx.x;
    if (i < NC * NC) {
        int c = i / NC, c2 = i % NC;
        float s = 0.0f;
        for (int d = 0; d < D; d++) s += E[(size_t)c * D + d] * E[(size_t)c2 * D + d];
        G[i] = s;
    }
}

__global__ void sim_attn_kernel(const float* __restrict__ QK, const float* __restrict__ qa,
                                const float* __restrict__ aq, const float* __restrict__ Eq,
                                const float* __restrict__ Ek, const float* __restrict__ G,
                                float* __restrict__ P, float* __restrict__ Wout) {
    int t = blockIdx.x, b = blockIdx.y;
    int s = threadIdx.x;                 // 128 threads
    int lane = s & 31, wd = s >> 5;
    __shared__ float g[NC * NC];
    __shared__ float part[4];
    __shared__ float pv[T];
    if (s < NC * NC) g[s] = G[s];
    __syncthreads();

    float f1[NC], f2[NC];
    const float* r1 = qa + (((size_t)b * T + t) * T + s) * NC;
    const float* r2 = aq + (((size_t)b * T + s) * T + t) * NC;
    #pragma unroll
    for (int c = 0; c < NC; c++) { f1[c] = r1[c]; f2[c] = r2[c]; }

    float sc = QK[((size_t)b * T + t) * T + s];
    const float* eq = Eq + ((size_t)b * T + t) * NC;
    const float* ek = Ek + ((size_t)b * T + s) * NC;
    #pragma unroll
    for (int c = 0; c < NC; c++) sc += f1[c] * ek[c] + f2[c] * eq[c];
    #pragma unroll
    for (int c = 0; c < NC; c++)
        #pragma unroll
        for (int c2 = 0; c2 < NC; c2++)
            sc += f1[c] * g[c * NC + c2] * f2[c2];

    float m = warp_max(sc);
    if (lane == 0) part[wd] = m;
    __syncthreads();
    float m1 = fmaxf(fmaxf(part[0], part[1]), fmaxf(part[2], part[3]));
    float e1 = expf(sc - m1);
    float ssum = warp_sum(e1);
    if (lane == 0) part[wd] = ssum;
    __syncthreads();
    float p = e1 / (part[0] + part[1] + part[2] + part[3]);

    float l = 1000.0f * p;
    m = warp_max(l);
    __syncthreads();
    if (lane == 0) part[wd] = m;
    __syncthreads();
    float m2 = fmaxf(fmaxf(part[0], part[1]), fmaxf(part[2], part[3]));
    float e2 = expf(l - m2);
    ssum = warp_sum(e2);
    __syncthreads();
    if (lane == 0) part[wd] = ssum;
    __syncthreads();
    float p2 = e2 / (part[0] + part[1] + part[2] + part[3]);
    p2 = fminf(fmaxf(p2, 0.0f), 1.0f);

    P[((size_t)b * T + t) * T + s] = p2;
    pv[s] = p2;
    __syncthreads();

    #pragma unroll
    for (int c = 0; c < NC; c++) {
        float v = warp_sum(pv[s] * f2[c]);
        __syncthreads();
        if (lane == 0) part[wd] = v;
        __syncthreads();
        if (s == 0) Wout[((size_t)b * T + t) * NC + c] = part[0] + part[1] + part[2] + part[3];
    }
}

__global__ void final_kernel(const float* __restrict__ pk, const float* __restrict__ Wm,
                             const float* __restrict__ E, const float* __restrict__ clsw,
                             const float* __restrict__ clsb, float* __restrict__ out) {
    int b = blockIdx.x;
    int d = threadIdx.x;
    __shared__ float wm[NC];
    __shared__ float red[512];

    if (d < NC) {
        float s = 0.0f;
        for (int t = 0; t < T; t++) s += Wm[((size_t)b * T + t) * NC + d];
        wm[d] = s * (1.0f / T);
    }
    __syncthreads();

    float s = 0.0f;
    for (int t = 0; t < T; t++) s += pk[((size_t)b * T + t) * D + d];
    s *= (1.0f / T);
    #pragma unroll
    for (int c = 0; c < NC; c++) s += wm[c] * E[(size_t)c * D + d];

    for (int j = 0; j < 3; j++) {
        red[d] = s * clsw[(size_t)d * 3 + j];
        __syncthreads();
        for (int off = 256; off > 0; off >>= 1) { if (d < off) red[d] += red[d + off]; __syncthreads(); }
        if (d == 0) out[b * 3 + j] = red[0] + clsb[j];
        __syncthreads();
    }
}

// ---------------- host orchestration ----------------------------------------
static inline void g_launch(int transB,
                            const float* A0, const float* A1, const float* A2,
                            const float* W0, const float* W1, const float* W2,
                            const float* b0, const float* b1, const float* b2,
                            float* C0, float* C1, float* C2,
                            int M, int N, int K, int lda, int ldb, int ldc,
                            int act, int nH,
                            long long sA, long long hA, long long sB, long long hB,
                            long long sC, long long hC, int zPerSet, int nz) {
    dim3 grid(N / 64, M / 64, nz);
    if (transB)
        gemm_tf32<1><<<grid, 256>>>(A0, A1, A2, W0, W1, W2, b0, b1, b2, C0, C1, C2,
                                    M, N, K, lda, ldb, ldc, act, nH,
                                    sA, hA, sB, hB, sC, hC, zPerSet);
    else
        gemm_tf32<0><<<grid, 256>>>(A0, A1, A2, W0, W1, W2, b0, b1, b2, C0, C1, C2,
                                    M, N, K, lda, ldb, ldc, act, nH,
                                    sA, hA, sB, hB, sC, hC, zPerSet);
}

extern "C" void kernel_launch(void* const* d_in, const int* in_sizes, int n_in,
                              void* d_out, int out_size) {
    const float* q_emb   = (const float*)d_in[0];
    const float* a_emb   = (const float*)d_in[1];
    const float* qa_rel  = (const float*)d_in[2];
    const float* aq_rel  = (const float*)d_in[3];
    const float* conceptE= (const float*)d_in[4];
    const float* pos_emb = (const float*)d_in[5];
    const float* pe_w    = (const float*)d_in[6];
    const float* pe_b    = (const float*)d_in[7];
    const float* Wq      = (const float*)d_in[8];
    const float* bq      = (const float*)d_in[9];
    const float* Wk      = (const float*)d_in[10];
    const float* bk      = (const float*)d_in[11];
    const float* Wv      = (const float*)d_in[12];
    const float* bv      = (const float*)d_in[13];
    const float* Wo      = (const float*)d_in[14];
    const float* bo      = (const float*)d_in[15];
    const float* ff1w    = (const float*)d_in[16];
    const float* ff1b    = (const float*)d_in[17];
    const float* ff2w    = (const float*)d_in[18];
    const float* ff2b    = (const float*)d_in[19];
    const float* lninw   = (const float*)d_in[20];
    const float* lninb   = (const float*)d_in[21];
    const float* lnoutw  = (const float*)d_in[22];
    const float* lnoutb  = (const float*)d_in[23];
    const float* simWq   = (const float*)d_in[24];
    const float* simbq   = (const float*)d_in[25];
    const float* simWk   = (const float*)d_in[26];
    const float* simbk   = (const float*)d_in[27];
    const float* clsw    = (const float*)d_in[28];
    const float* clsb    = (const float*)d_in[29];
    float* out = (float*)d_out;

    float* base = nullptr;
    cudaGetSymbolAddress((void**)&base, g_scratch);

    float* X   = base + OFF_X;
    float* Qb  = base + OFF_Q;
    float* Kb  = base + OFF_K;
    float* Vb  = base + OFF_V;
    float* T0  = base + OFF_T0;
    float* T1b = base + OFF_T1;
    float* Hb  = base + OFF_H;
    float* FFN = base + OFF_FFN;
    float* QKb = base + OFF_QK;
    float* Pb  = base + OFF_P;
    float* EQb = base + OFF_EQ;
    float* EKb = base + OFF_EK;
    float* Gb  = base + OFF_G;
    float* Wb  = base + OFF_W;
    float* PKb = base + OFF_PK;

    static const int ATTN_SMEM = (64 + 128) * APAD * 4;
    cudaFuncSetAttribute(fused_attn, cudaFuncAttributeMaxDynamicSharedMemorySize, ATTN_SMEM);

    add_pos_ln_kernel<<<M2 / 2, 128>>>(q_emb, pos_emb, pe_w, pe_b, X);
    add_pos_ln_kernel<<<M2 / 2, 128>>>(a_emb, pos_emb, pe_w, pe_b, X + (size_t)(M2 / 2) * D);

    for (int i = 0; i < NL; i++) {
        const float* wq = Wq + (size_t)i * D * D;
        const float* wk = Wk + (size_t)i * D * D;
        const float* wv = Wv + (size_t)i * D * D;
        const float* wo = Wo + (size_t)i * D * D;

        // fused QKV: 3 sets, one launch (grid 8x16x3 = 384)
        g_launch(0, X, X, X, wq, wk, wv,
                 bq + (size_t)i * D, bk + (size_t)i * D, bv + (size_t)i * D,
                 Qb, Kb, Vb,
                 M2, D, D, D, D, D, 0, 1, 0, 0, 0, 0, 0, 0, 1, 3);

        // fused attention: grid (2, 32)
        fused_attn<<<dim3(2, 32), 256, ATTN_SMEM>>>(Qb, Kb, Vb, T0);

        // output projection (grid 128)
        g_launch(0, T0, 0, 0, wo, 0, 0, bo + (size_t)i * D, 0, 0, T1b, 0, 0,
                 M2, D, D, D, D, D, 0, 1, 0, 0, 0, 0, 0, 0, 1, 1);

        residual_ln_kernel<<<M2, 128>>>(X, T1b, Hb, lninw + (size_t)i * D, lninb + (size_t)i * D);

        g_launch(0, Hb, 0, 0, ff1w + (size_t)i * D * DFF, 0, 0, ff1b + (size_t)i * DFF, 0, 0, FFN, 0, 0,
                 M2, DFF, D, D, DFF, DFF, 1, 1, 0, 0, 0, 0, 0, 0, 1, 1);
        g_launch(0, FFN, 0, 0, ff2w + (size_t)i * DFF * D, 0, 0, ff2b + (size_t)i * D, 0, 0, T1b, 0, 0,
                 M2, D, DFF, DFF, D, D, 0, 1, 0, 0, 0, 0, 0, 0, 1, 1);

        residual_ln_kernel<<<M2, 128>>>(X, T1b, X, lnoutw + (size_t)i * D, lnoutb + (size_t)i * D);
    }

    // --- sim head ---
    g_launch(0, X, X + (size_t)(M2 / 2) * D, 0, simWq, simWk, 0, simbq, simbk, 0, Qb, Kb, 0,
             M2 / 2, D, D, D, D, D, 0, 1, 0, 0, 0, 0, 0, 0, 1, 2);

    edot_kernel<<<M2 / 2, 256>>>(Qb, conceptE, EQb);
    edot_kernel<<<M2 / 2, 256>>>(Kb, conceptE, EKb);
    gram_kernel<<<1, 32>>>(conceptE, Gb);

    // QK[b] = q_sim[b] @ k_sim[b]^T
    g_launch(1, Qb, 0, 0, Kb, 0, 0, 0, 0, 0, QKb, 0, 0,
             T, T, D, D, D, T, 0, 1,
             (long long)T * D, 0, (long long)T * D, 0, (long long)T * T, 0, 4, 4);

    sim_attn_kernel<<<dim3(T, Bb), 128>>>(QKb, qa_rel, aq_rel, EQb, EKb, Gb, Pb, Wb);

    // pk[b] = P[b] @ k_sim[b]
    g_launch(0, Pb, 0, 0, Kb, 0, 0, 0, 0, 0, PKb, 0, 0,
             T, D, T, T, D, D, 0, 1,
             (long long)T * T, 0, (long long)T * D, 0, (long long)T * D, 0, 4, 4);

    final_kernel<<<Bb, 512>>>(PKb, Wb, conceptE, clsw, clsb, out);
}